// round 16
// baseline (speedup 1.0000x reference)
#include <cuda_runtime.h>
#include <cuda_fp16.h>
#include <cstdint>

// Problem dims (fixed): B=8, N=2048, C=1024, D=16
#define BSZ 8
#define SEQ 2048
#define DM  1024
#define DS  16
#define TOT (BSZ * SEQ * DM)   // 16,777,216

#define NC    32               // scan chunks
#define CHUNK (SEQ / NC)       // 64 steps per chunk
#define DH    (DS / 2)         // states per lane (pair d-split, R12 winner)

#define LOG2E 1.4426950408889634f

// Scratch (allocation-free rule: static __device__ globals)
__device__ float  g_xf[(size_t)TOT];        // conv output fp32 (scan input)
__device__ float  g_dt[(size_t)TOT];        // dt after sigmoid scaling
__device__ __half g_xh[(size_t)TOT];        // fp16(xf) for GEMM
__device__ __half g_wh[(size_t)DM * DM];    // fp16(dt_w)
__device__ float  g_A2[(size_t)DM * DS];    // -softplus(a_log)*log2e
// chunked-scan state, layout [b][ch][d][c]  (c fastest -> coalesced)
__device__ float g_P    [(size_t)BSZ * NC * DS * DM];  // chunk decay products
__device__ float g_Sloc [(size_t)BSZ * NC * DS * DM];  // chunk-local end states
__device__ float g_sinit[(size_t)BSZ * NC * DS * DM];  // per-chunk initial states

__device__ __forceinline__ float ex2f(float x) {
    float y; asm("ex2.approx.f32 %0, %1;" : "=f"(y) : "f"(x)); return y;
}
__device__ __forceinline__ float rcpf(float x) {
    float y; asm("rcp.approx.f32 %0, %1;" : "=f"(y) : "f"(x)); return y;
}
__device__ __forceinline__ void cp16s(uint32_t s, const void* g) {
    asm volatile("cp.async.cg.shared.global [%0], [%1], 16;" :: "r"(s), "l"(g));
}
__device__ __forceinline__ uint32_t smem_u32(const void* p) {
    uint32_t a;
    asm("{ .reg .u64 t; cvta.to.shared.u64 t, %1; cvt.u32.u64 %0, t; }" : "=r"(a) : "l"(p));
    return a;
}
#define LDSM4(r0, r1, r2, r3, addr) \
    asm volatile("ldmatrix.sync.aligned.m8n8.x4.shared.b16 {%0,%1,%2,%3}, [%4];" \
                 : "=r"(r0), "=r"(r1), "=r"(r2), "=r"(r3) : "r"(addr))

// ---------------------------------------------------------------------------
// Kernel 0: precompute A2 table (tiny, once per launch)
// ---------------------------------------------------------------------------
__global__ void aprep_kernel(const float* __restrict__ a_log)
{
    int i = blockIdx.x * blockDim.x + threadIdx.x;
    if (i >= DM * DS) return;
    float z  = a_log[i];
    float sp = fmaxf(z, 0.0f) + log1pf(__expf(-fabsf(z)));   // softplus
    g_A2[i] = -sp * LOG2E;
}

// ---------------------------------------------------------------------------
// Kernel 1: depthwise conv k=3 pad=1 along sequence. float4-vectorized,
// 2 independent elements per thread for MLP (latency-bound kernel).
// ---------------------------------------------------------------------------
__global__ void conv_kernel(const float4* __restrict__ x4,
                            const float4* __restrict__ cw4,
                            const float4* __restrict__ cb4)
{
    int tid0 = blockIdx.x * blockDim.x + threadIdx.x;    // 0 .. TOT/8-1
#pragma unroll
    for (int rep = 0; rep < 2; ++rep) {
        int i4 = tid0 + rep * (TOT / 8);
        int c4 = i4 & (DM / 4 - 1);
        int n  = (i4 >> 8) & (SEQ - 1);

        float4 wa = cw4[c4 * 3 + 0];
        float4 wb = cw4[c4 * 3 + 1];
        float4 wc = cw4[c4 * 3 + 2];
        float4 bb = cb4[c4];

        const float4 z = make_float4(0.f, 0.f, 0.f, 0.f);
        float4 xm = (n > 0)       ? x4[i4 - DM / 4] : z;
        float4 xc = x4[i4];
        float4 xp = (n < SEQ - 1) ? x4[i4 + DM / 4] : z;

        float4 y;
        y.x = fmaf(wa.x, xm.x, fmaf(wa.y, xc.x, fmaf(wa.z, xp.x, bb.x)));
        y.y = fmaf(wa.w, xm.y, fmaf(wb.x, xc.y, fmaf(wb.y, xp.y, bb.y)));
        y.z = fmaf(wb.z, xm.z, fmaf(wb.w, xc.z, fmaf(wc.x, xp.z, bb.z)));
        y.w = fmaf(wc.y, xm.w, fmaf(wc.z, xc.w, fmaf(wc.w, xp.w, bb.w)));

        ((float4*)g_xf)[i4] = y;

        __half2 p01 = __floats2half2_rn(y.x, y.y);
        __half2 p23 = __floats2half2_rn(y.z, y.w);
        uint2 hp;
        hp.x = *(uint32_t*)&p01; hp.y = *(uint32_t*)&p23;
        *(uint2*)&g_xh[(size_t)i4 * 4] = hp;
    }
}

// ---------------------------------------------------------------------------
// Kernel 1b: convert dt_w to fp16
// ---------------------------------------------------------------------------
__global__ void wsplit_kernel(const float4* __restrict__ w4)
{
    int i4 = blockIdx.x * blockDim.x + threadIdx.x;
    if (i4 >= DM * DM / 4) return;
    float4 v = w4[i4];
    __half2 p01 = __floats2half2_rn(v.x, v.y);
    __half2 p23 = __floats2half2_rn(v.z, v.w);
    uint2 hp;
    hp.x = *(uint32_t*)&p01; hp.y = *(uint32_t*)&p23;
    *(uint2*)&g_wh[(size_t)i4 * 4] = hp;
}

// ---------------------------------------------------------------------------
// Kernel 2: dt GEMM, single-pass fp16 (fp32 accumulate).
// 4-STAGE cp.async ring (stage = kt & 3, prefetch distance 2, wait_group 1)
// with ONE barrier per k-iteration: the top barrier (post-wait) guarantees
// all warps finished compute on kt-1 and earlier, and the load target
// (kt+2 mod 4) is never a stage read by kt or in-flight kt+1 loads.
// CTA 128x128x32, 8 warps x (32x64), ldmatrix fragments.
// ---------------------------------------------------------------------------
#define TBK 32
#define SPAD 40
#define A_B (128 * SPAD * 2)           // 10240 bytes per array
#define STGB (2 * A_B)                 // A + B = 20480 bytes per stage
#define NSTG 4
#define GEMM_SMEM (NSTG * STGB)        // 81920 bytes

__device__ __forceinline__ void mma_f16(float* c, const uint32_t* a, const uint32_t* b) {
    asm volatile(
        "mma.sync.aligned.m16n8k16.row.col.f32.f16.f16.f32 "
        "{%0,%1,%2,%3},{%4,%5,%6,%7},{%8,%9},{%0,%1,%2,%3};"
        : "+f"(c[0]), "+f"(c[1]), "+f"(c[2]), "+f"(c[3])
        : "r"(a[0]), "r"(a[1]), "r"(a[2]), "r"(a[3]), "r"(b[0]), "r"(b[1]));
}

__global__ __launch_bounds__(256)
void gemm_dt_kernel(const float* __restrict__ bias)
{
    extern __shared__ __half sm[];
    const uint32_t smb = smem_u32(sm);

    const int tid  = threadIdx.x;
    const int lane = tid & 31;
    const int warp = tid >> 5;
    const int wm   = warp >> 1;          // 0..3 -> 32-row slices
    const int wn   = warp & 1;           // 0..1 -> 64-col slices
    const int qr   = lane >> 2;
    const int qc   = lane & 3;
    const int bm   = blockIdx.y * 128;
    const int bn   = blockIdx.x * 128;

    // ldmatrix per-lane fragment addressing (verified R12)
    const int lr  = lane & 7;
    const int g01 = (lane >> 3) & 1;
    const int g23 = lane >> 4;
    const int aRow    = wm * 32 + g01 * 8 + lr;
    const int aColOff = g23 * 8;
    const int bRow    = wn * 64 + g23 * 8 + lr;
    const int bColOff = g01 * 8;

    float acc[2][8][4];
#pragma unroll
    for (int mt = 0; mt < 2; ++mt)
#pragma unroll
        for (int nt = 0; nt < 8; ++nt)
#pragma unroll
            for (int r = 0; r < 4; ++r) acc[mt][nt][r] = 0.0f;

    auto load_stage = [&](int st, int k0) {
        uint32_t base = smb + (uint32_t)st * STGB;
#pragma unroll
        for (int i = 0; i < 2; ++i) {
            int f   = tid + i * 256;              // 0..511
            int row = f >> 2;
            int k8  = (f & 3) << 3;
            size_t ga = (size_t)(bm + row) * DM + k0 + k8;
            size_t gb = (size_t)(bn + row) * DM + k0 + k8;
            uint32_t so = (uint32_t)(row * SPAD + k8) * 2;
            cp16s(base + so,       &g_xh[ga]);
            cp16s(base + A_B + so, &g_wh[gb]);
        }
        asm volatile("cp.async.commit_group;");
    };

    const int KT = DM / TBK;   // 32
    load_stage(0, 0);
    load_stage(1, TBK);

    for (int kt = 0; kt < KT; ++kt) {
        if (kt == KT - 1) {
            asm volatile("cp.async.wait_group 0;");
        } else {
            asm volatile("cp.async.wait_group 1;");
        }
        __syncthreads();                           // single barrier per kt
        if (kt + 2 < KT) load_stage((kt + 2) & 3, (kt + 2) * TBK);

        uint32_t sbase = smb + (uint32_t)(kt & 3) * STGB;
        uint32_t aBase = sbase + (uint32_t)(aRow * SPAD + aColOff) * 2;
        uint32_t bBase = sbase + A_B + (uint32_t)(bRow * SPAD + bColOff) * 2;

#pragma unroll
        for (int kst = 0; kst < TBK; kst += 16) {
            uint32_t kb = (uint32_t)(kst * 2);
            uint32_t ah[2][4], bh[8][2];
#pragma unroll
            for (int mt = 0; mt < 2; ++mt) {
                uint32_t aoff = aBase + (uint32_t)(mt * 16 * SPAD) * 2 + kb;
                LDSM4(ah[mt][0], ah[mt][1], ah[mt][2], ah[mt][3], aoff);
            }
#pragma unroll
            for (int p = 0; p < 4; ++p) {
                uint32_t boff = bBase + (uint32_t)(p * 16 * SPAD) * 2 + kb;
                LDSM4(bh[2 * p][0], bh[2 * p][1], bh[2 * p + 1][0], bh[2 * p + 1][1], boff);
            }
#pragma unroll
            for (int mt = 0; mt < 2; ++mt)
#pragma unroll
                for (int nt = 0; nt < 8; ++nt)
                    mma_f16(acc[mt][nt], ah[mt], bh[nt]);
        }
        // no trailing barrier: load target (kt+2)&3 is disjoint from stages
        // being read (kt&3) and in-flight ((kt+1)&3); top barrier orders reuse.
    }

    // epilogue: bias + sigmoid scaling
#pragma unroll
    for (int mt = 0; mt < 2; ++mt) {
#pragma unroll
        for (int nt = 0; nt < 8; ++nt) {
            int row = bm + wm * 32 + mt * 16 + qr;
            int col = bn + wn * 64 + nt * 8 + qc * 2;
            float2 bb = *(const float2*)&bias[col];
#pragma unroll
            for (int half = 0; half < 2; ++half) {
                int r = row + half * 8;
                float r0 = acc[mt][nt][half * 2 + 0] + bb.x;
                float r1 = acc[mt][nt][half * 2 + 1] + bb.y;
                float s0 = rcpf(1.0f + ex2f(-r0 * LOG2E));
                float s1 = rcpf(1.0f + ex2f(-r1 * LOG2E));
                float2 v;
                v.x = fmaf(s0, 0.099f, 0.001f);
                v.y = fmaf(s1, 0.099f, 0.001f);
                *(float2*)&g_dt[(size_t)r * DM + col] = v;
            }
        }
    }
}

// ---------------------------------------------------------------------------
// Kernel 3a: chunk-local reduction, pair d-SPLIT (R12 winner, unchanged).
// ---------------------------------------------------------------------------
__global__ __launch_bounds__(256)
void scan_pass1(const float* __restrict__ Bm)
{
    int bb   = blockIdx.z;
    int ch   = blockIdx.y;
    int half = threadIdx.x & 1;
    int c    = blockIdx.x * 128 + (threadIdx.x >> 1);
    int d0   = half * DH;

    float A2[DH], Bv[DH], s[DH];
#pragma unroll
    for (int j = 0; j < DH; ++j) {
        A2[j] = g_A2[c * DS + d0 + j];
        Bv[j] = Bm  [c * DS + d0 + j];
        s[j]  = 0.0f;
    }

    size_t base = ((size_t)bb * SEQ + (size_t)ch * CHUNK) * DM + c;
    const float* pdt = g_dt + base;
    const float* pxf = g_xf + base;

    float cum = 0.0f;
    float ndt = __ldcs(pdt), nxf = __ldcs(pxf);
    for (int t = 0; t < CHUNK; ++t) {
        float dt = ndt, xf = nxf;
        if (t + 1 < CHUNK) {
            ndt = __ldcs(pdt + (size_t)(t + 1) * DM);
            nxf = __ldcs(pxf + (size_t)(t + 1) * DM);
        }
        cum += dt;
        float u = dt * xf;
#pragma unroll
        for (int j = 0; j < DH; ++j) {
            float e = ex2f(dt * A2[j]);
            s[j] = fmaf(e, s[j], u * Bv[j]);
        }
    }

    size_t sb = (((size_t)bb * NC + ch) * DS + d0) * DM + c;
#pragma unroll
    for (int j = 0; j < DH; ++j) {
        g_Sloc[sb + (size_t)j * DM] = s[j];
        g_P   [sb + (size_t)j * DM] = ex2f(A2[j] * cum);
    }
}

// ---------------------------------------------------------------------------
// Kernel 3b: combine across chunks. One thread per (b, d, c).
// ---------------------------------------------------------------------------
__global__ __launch_bounds__(256)
void scan_pass2()
{
    int t  = blockIdx.x * blockDim.x + threadIdx.x;
    int bb = t / (DS * DM);
    int k  = t - bb * (DS * DM);

    float s = 0.0f;
    size_t stride = (size_t)DS * DM;
    size_t ix = ((size_t)bb * NC) * stride + k;
    for (int ch = 0; ch < NC; ++ch, ix += stride) {
        g_sinit[ix] = s;
        s = fmaf(g_P[ix], s, g_Sloc[ix]);
    }
}

// ---------------------------------------------------------------------------
// Kernel 3c: seeded rescan, pair d-SPLIT + 1 shfl (R12 winner, unchanged).
// ---------------------------------------------------------------------------
__global__ __launch_bounds__(256)
void scan_pass3(const float* __restrict__ Bm,
                const float* __restrict__ Cm,
                float* __restrict__ out)
{
    int bb   = blockIdx.z;
    int ch   = blockIdx.y;
    int half = threadIdx.x & 1;
    int c    = blockIdx.x * 128 + (threadIdx.x >> 1);
    int d0   = half * DH;

    float A2[DH], Bv[DH], Cv[DH], s[DH];
    size_t sb = (((size_t)bb * NC + ch) * DS + d0) * DM + c;
#pragma unroll
    for (int j = 0; j < DH; ++j) {
        A2[j] = g_A2[c * DS + d0 + j];
        Bv[j] = Bm  [c * DS + d0 + j];
        Cv[j] = Cm  [c * DS + d0 + j];
        s[j]  = g_sinit[sb + (size_t)j * DM];
    }

    size_t base = ((size_t)bb * SEQ + (size_t)ch * CHUNK) * DM + c;
    const float* pdt = g_dt + base;
    const float* pxf = g_xf + base;
    float*       py  = out  + base;

    float ndt = __ldcs(pdt), nxf = __ldcs(pxf);
    for (int t = 0; t < CHUNK; ++t) {
        float dt = ndt, xf = nxf;
        if (t + 1 < CHUNK) {
            ndt = __ldcs(pdt + (size_t)(t + 1) * DM);
            nxf = __ldcs(pxf + (size_t)(t + 1) * DM);
        }
        float u = dt * xf;
        float a0 = 0.f, a1 = 0.f;
#pragma unroll
        for (int j = 0; j < DH; j += 2) {
            float e0 = ex2f(dt * A2[j + 0]);
            float e1 = ex2f(dt * A2[j + 1]);
            s[j + 0] = fmaf(e0, s[j + 0], u * Bv[j + 0]);
            s[j + 1] = fmaf(e1, s[j + 1], u * Bv[j + 1]);
            a0 = fmaf(s[j + 0], Cv[j + 0], a0);
            a1 = fmaf(s[j + 1], Cv[j + 1], a1);
        }
        float acc = a0 + a1;
        float tot = acc + __shfl_xor_sync(0xFFFFFFFFu, acc, 1);
        if (half == 0) py[(size_t)t * DM] = tot;
    }
}

// ---------------------------------------------------------------------------
extern "C" void kernel_launch(void* const* d_in, const int* in_sizes, int n_in,
                              void* d_out, int out_size)
{
    const float* x      = (const float*)d_in[0];  // (8,2048,1024)
    const float* a_log  = (const float*)d_in[1];  // (1024,16)
    const float* b      = (const float*)d_in[2];  // (1024,16)
    const float* c      = (const float*)d_in[3];  // (1024,16)
    const float* dt_w   = (const float*)d_in[4];  // (1024,1024)
    const float* dt_b   = (const float*)d_in[5];  // (1024,)
    const float* conv_w = (const float*)d_in[6];  // (1024,1,3)
    const float* conv_b = (const float*)d_in[7];  // (1024,)
    float* out = (float*)d_out;                   // (8,2048,1024)

    // 0) A2 table + dt_w fp16 conversion (tiny)
    aprep_kernel<<<(DM * DS + 255) / 256, 256>>>(a_log);
    wsplit_kernel<<<(DM * DM / 4 + 255) / 256, 256>>>((const float4*)dt_w);

    // 1) depthwise conv -> g_xf (fp32) + g_xh (fp16), 2 elems/thread
    conv_kernel<<<TOT / 8 / 256, 256>>>(
        (const float4*)x, (const float4*)conv_w, (const float4*)conv_b);

    // 2) dt GEMM (+sigmoid) -> g_dt  (fp16, 4-stage ring, 1 barrier/iter)
    cudaFuncSetAttribute(gemm_dt_kernel,
                         cudaFuncAttributeMaxDynamicSharedMemorySize, GEMM_SMEM);
    dim3 ggrid(DM / 128, (BSZ * SEQ) / 128);      // (8, 128) = 1024 CTAs
    gemm_dt_kernel<<<ggrid, 256, GEMM_SMEM>>>(dt_b);

    // 3) chunked selective scan: reduce -> combine -> seeded rescan
    dim3 sgrid(DM / 128, NC, BSZ);                // (8, 32, 8)
    scan_pass1<<<sgrid, 256>>>(b);
    scan_pass2<<<(BSZ * DS * DM) / 256, 256>>>();
    scan_pass3<<<sgrid, 256>>>(b, c, out);
}

// round 17
// speedup vs baseline: 1.1628x; 1.1628x over previous
#include <cuda_runtime.h>
#include <cuda_fp16.h>
#include <cstdint>

// Problem dims (fixed): B=8, N=2048, C=1024, D=16
#define BSZ 8
#define SEQ 2048
#define DM  1024
#define DS  16
#define TOT (BSZ * SEQ * DM)   // 16,777,216

#define NC    32               // scan chunks
#define CHUNK (SEQ / NC)       // 64 steps per chunk
#define DH    (DS / 2)         // states per lane (pair d-split, R12 winner)
#define PF    4                // scan prefetch batch (steps)

#define LOG2E 1.4426950408889634f

// Scratch (allocation-free rule: static __device__ globals)
__device__ float  g_xf[(size_t)TOT];        // conv output fp32 (scan input)
__device__ float  g_dt[(size_t)TOT];        // dt after sigmoid scaling
__device__ __half g_xh[(size_t)TOT];        // fp16(xf) for GEMM
__device__ __half g_wh[(size_t)DM * DM];    // fp16(dt_w)
__device__ float  g_A2[(size_t)DM * DS];    // -softplus(a_log)*log2e
// chunked-scan state, layout [b][ch][d][c]  (c fastest -> coalesced)
__device__ float g_P    [(size_t)BSZ * NC * DS * DM];  // chunk decay products
__device__ float g_Sloc [(size_t)BSZ * NC * DS * DM];  // chunk-local end states
__device__ float g_sinit[(size_t)BSZ * NC * DS * DM];  // per-chunk initial states

__device__ __forceinline__ float ex2f(float x) {
    float y; asm("ex2.approx.f32 %0, %1;" : "=f"(y) : "f"(x)); return y;
}
__device__ __forceinline__ float rcpf(float x) {
    float y; asm("rcp.approx.f32 %0, %1;" : "=f"(y) : "f"(x)); return y;
}
__device__ __forceinline__ void cp16s(uint32_t s, const void* g) {
    asm volatile("cp.async.cg.shared.global [%0], [%1], 16;" :: "r"(s), "l"(g));
}
__device__ __forceinline__ uint32_t smem_u32(const void* p) {
    uint32_t a;
    asm("{ .reg .u64 t; cvta.to.shared.u64 t, %1; cvt.u32.u64 %0, t; }" : "=r"(a) : "l"(p));
    return a;
}
#define LDSM4(r0, r1, r2, r3, addr) \
    asm volatile("ldmatrix.sync.aligned.m8n8.x4.shared.b16 {%0,%1,%2,%3}, [%4];" \
                 : "=r"(r0), "=r"(r1), "=r"(r2), "=r"(r3) : "r"(addr))

// ---------------------------------------------------------------------------
// Kernel 0: precompute A2 table (tiny, once per launch)
// ---------------------------------------------------------------------------
__global__ void aprep_kernel(const float* __restrict__ a_log)
{
    int i = blockIdx.x * blockDim.x + threadIdx.x;
    if (i >= DM * DS) return;
    float z  = a_log[i];
    float sp = fmaxf(z, 0.0f) + log1pf(__expf(-fabsf(z)));   // softplus
    g_A2[i] = -sp * LOG2E;
}

// ---------------------------------------------------------------------------
// Kernel 1: depthwise conv k=3 pad=1 along sequence. float4-vectorized,
// 2 independent elements per thread (R15 keeper).
// ---------------------------------------------------------------------------
__global__ void conv_kernel(const float4* __restrict__ x4,
                            const float4* __restrict__ cw4,
                            const float4* __restrict__ cb4)
{
    int tid0 = blockIdx.x * blockDim.x + threadIdx.x;    // 0 .. TOT/8-1
#pragma unroll
    for (int rep = 0; rep < 2; ++rep) {
        int i4 = tid0 + rep * (TOT / 8);
        int c4 = i4 & (DM / 4 - 1);
        int n  = (i4 >> 8) & (SEQ - 1);

        float4 wa = cw4[c4 * 3 + 0];
        float4 wb = cw4[c4 * 3 + 1];
        float4 wc = cw4[c4 * 3 + 2];
        float4 bb = cb4[c4];

        const float4 z = make_float4(0.f, 0.f, 0.f, 0.f);
        float4 xm = (n > 0)       ? x4[i4 - DM / 4] : z;
        float4 xc = x4[i4];
        float4 xp = (n < SEQ - 1) ? x4[i4 + DM / 4] : z;

        float4 y;
        y.x = fmaf(wa.x, xm.x, fmaf(wa.y, xc.x, fmaf(wa.z, xp.x, bb.x)));
        y.y = fmaf(wa.w, xm.y, fmaf(wb.x, xc.y, fmaf(wb.y, xp.y, bb.y)));
        y.z = fmaf(wb.z, xm.z, fmaf(wb.w, xc.z, fmaf(wc.x, xp.z, bb.z)));
        y.w = fmaf(wc.y, xm.w, fmaf(wc.z, xc.w, fmaf(wc.w, xp.w, bb.w)));

        ((float4*)g_xf)[i4] = y;

        __half2 p01 = __floats2half2_rn(y.x, y.y);
        __half2 p23 = __floats2half2_rn(y.z, y.w);
        uint2 hp;
        hp.x = *(uint32_t*)&p01; hp.y = *(uint32_t*)&p23;
        *(uint2*)&g_xh[(size_t)i4 * 4] = hp;
    }
}

// ---------------------------------------------------------------------------
// Kernel 1b: convert dt_w to fp16
// ---------------------------------------------------------------------------
__global__ void wsplit_kernel(const float4* __restrict__ w4)
{
    int i4 = blockIdx.x * blockDim.x + threadIdx.x;
    if (i4 >= DM * DM / 4) return;
    float4 v = w4[i4];
    __half2 p01 = __floats2half2_rn(v.x, v.y);
    __half2 p23 = __floats2half2_rn(v.z, v.w);
    uint2 hp;
    hp.x = *(uint32_t*)&p01; hp.y = *(uint32_t*)&p23;
    *(uint2*)&g_wh[(size_t)i4 * 4] = hp;
}

// ---------------------------------------------------------------------------
// Kernel 2: dt GEMM, single-pass fp16 (fp32 accumulate) -- EXACT R14 winner
// (2-stage cp.async, wait_group 0, two barriers/iter; 116us measured).
// CTA 128x128x32, 8 warps x (32x64), ldmatrix fragments.
// ---------------------------------------------------------------------------
#define TBK 32
#define SPAD 40
#define A_B (128 * SPAD * 2)           // 10240 bytes per array
#define STGB (2 * A_B)                 // A + B = 20480 bytes per stage
#define GEMM_SMEM (2 * STGB)           // 40960 bytes

__device__ __forceinline__ void mma_f16(float* c, const uint32_t* a, const uint32_t* b) {
    asm volatile(
        "mma.sync.aligned.m16n8k16.row.col.f32.f16.f16.f32 "
        "{%0,%1,%2,%3},{%4,%5,%6,%7},{%8,%9},{%0,%1,%2,%3};"
        : "+f"(c[0]), "+f"(c[1]), "+f"(c[2]), "+f"(c[3])
        : "r"(a[0]), "r"(a[1]), "r"(a[2]), "r"(a[3]), "r"(b[0]), "r"(b[1]));
}

__global__ __launch_bounds__(256)
void gemm_dt_kernel(const float* __restrict__ bias)
{
    extern __shared__ __half sm[];
    const uint32_t smb = smem_u32(sm);

    const int tid  = threadIdx.x;
    const int lane = tid & 31;
    const int warp = tid >> 5;
    const int wm   = warp >> 1;          // 0..3 -> 32-row slices
    const int wn   = warp & 1;           // 0..1 -> 64-col slices
    const int qr   = lane >> 2;
    const int qc   = lane & 3;
    const int bm   = blockIdx.y * 128;
    const int bn   = blockIdx.x * 128;

    const int lr  = lane & 7;
    const int g01 = (lane >> 3) & 1;
    const int g23 = lane >> 4;
    const int aRow    = wm * 32 + g01 * 8 + lr;
    const int aColOff = g23 * 8;
    const int bRow    = wn * 64 + g23 * 8 + lr;
    const int bColOff = g01 * 8;

    float acc[2][8][4];
#pragma unroll
    for (int mt = 0; mt < 2; ++mt)
#pragma unroll
        for (int nt = 0; nt < 8; ++nt)
#pragma unroll
            for (int r = 0; r < 4; ++r) acc[mt][nt][r] = 0.0f;

    auto load_stage = [&](int st, int k0) {
        uint32_t base = smb + (uint32_t)st * STGB;
#pragma unroll
        for (int i = 0; i < 2; ++i) {
            int f   = tid + i * 256;              // 0..511
            int row = f >> 2;
            int k8  = (f & 3) << 3;
            size_t ga = (size_t)(bm + row) * DM + k0 + k8;
            size_t gb = (size_t)(bn + row) * DM + k0 + k8;
            uint32_t so = (uint32_t)(row * SPAD + k8) * 2;
            cp16s(base + so,       &g_xh[ga]);
            cp16s(base + A_B + so, &g_wh[gb]);
        }
        asm volatile("cp.async.commit_group;");
    };

    const int KT = DM / TBK;   // 32
    load_stage(0, 0);

    for (int kt = 0; kt < KT; ++kt) {
        asm volatile("cp.async.wait_group 0;");
        __syncthreads();
        if (kt + 1 < KT) load_stage((kt + 1) & 1, (kt + 1) * TBK);

        uint32_t stage = smb + (uint32_t)(kt & 1) * STGB;
        uint32_t aBase = stage + (uint32_t)(aRow * SPAD + aColOff) * 2;
        uint32_t bBase = stage + A_B + (uint32_t)(bRow * SPAD + bColOff) * 2;

#pragma unroll
        for (int kst = 0; kst < TBK; kst += 16) {
            uint32_t kb = (uint32_t)(kst * 2);
            uint32_t ah[2][4], bh[8][2];
#pragma unroll
            for (int mt = 0; mt < 2; ++mt) {
                uint32_t aoff = aBase + (uint32_t)(mt * 16 * SPAD) * 2 + kb;
                LDSM4(ah[mt][0], ah[mt][1], ah[mt][2], ah[mt][3], aoff);
            }
#pragma unroll
            for (int p = 0; p < 4; ++p) {
                uint32_t boff = bBase + (uint32_t)(p * 16 * SPAD) * 2 + kb;
                LDSM4(bh[2 * p][0], bh[2 * p][1], bh[2 * p + 1][0], bh[2 * p + 1][1], boff);
            }
#pragma unroll
            for (int mt = 0; mt < 2; ++mt)
#pragma unroll
                for (int nt = 0; nt < 8; ++nt)
                    mma_f16(acc[mt][nt], ah[mt], bh[nt]);
        }
        __syncthreads();
    }

    // epilogue: bias + sigmoid scaling
#pragma unroll
    for (int mt = 0; mt < 2; ++mt) {
#pragma unroll
        for (int nt = 0; nt < 8; ++nt) {
            int row = bm + wm * 32 + mt * 16 + qr;
            int col = bn + wn * 64 + nt * 8 + qc * 2;
            float2 bb = *(const float2*)&bias[col];
#pragma unroll
            for (int half = 0; half < 2; ++half) {
                int r = row + half * 8;
                float r0 = acc[mt][nt][half * 2 + 0] + bb.x;
                float r1 = acc[mt][nt][half * 2 + 1] + bb.y;
                float s0 = rcpf(1.0f + ex2f(-r0 * LOG2E));
                float s1 = rcpf(1.0f + ex2f(-r1 * LOG2E));
                float2 v;
                v.x = fmaf(s0, 0.099f, 0.001f);
                v.y = fmaf(s1, 0.099f, 0.001f);
                *(float2*)&g_dt[(size_t)r * DM + col] = v;
            }
        }
    }
}

// ---------------------------------------------------------------------------
// Kernel 3a: chunk-local reduction, pair d-SPLIT + 4-step register prefetch.
// Per batch of 4 steps: 8 independent LDGs in flight over ~256 MUFU-cycles
// of compute, hiding L2/DRAM latency that 1-step prefetch exposed.
// ---------------------------------------------------------------------------
__global__ __launch_bounds__(256)
void scan_pass1(const float* __restrict__ Bm)
{
    int bb   = blockIdx.z;
    int ch   = blockIdx.y;
    int half = threadIdx.x & 1;
    int c    = blockIdx.x * 128 + (threadIdx.x >> 1);
    int d0   = half * DH;

    float A2[DH], Bv[DH], s[DH];
#pragma unroll
    for (int j = 0; j < DH; ++j) {
        A2[j] = g_A2[c * DS + d0 + j];
        Bv[j] = Bm  [c * DS + d0 + j];
        s[j]  = 0.0f;
    }

    size_t base = ((size_t)bb * SEQ + (size_t)ch * CHUNK) * DM + c;
    const float* pdt = g_dt + base;
    const float* pxf = g_xf + base;

    float ndt[PF], nxf[PF], cdt[PF], cxf[PF];
#pragma unroll
    for (int i = 0; i < PF; ++i) {
        ndt[i] = __ldcs(pdt + (size_t)i * DM);
        nxf[i] = __ldcs(pxf + (size_t)i * DM);
    }

    float cum = 0.0f;
    for (int blk = 0; blk < CHUNK / PF; ++blk) {
#pragma unroll
        for (int i = 0; i < PF; ++i) { cdt[i] = ndt[i]; cxf[i] = nxf[i]; }

        if (blk + 1 < CHUNK / PF) {
            const float* q1 = pdt + (size_t)(blk + 1) * PF * DM;
            const float* q2 = pxf + (size_t)(blk + 1) * PF * DM;
#pragma unroll
            for (int i = 0; i < PF; ++i) {
                ndt[i] = __ldcs(q1 + (size_t)i * DM);
                nxf[i] = __ldcs(q2 + (size_t)i * DM);
            }
        }

#pragma unroll
        for (int i = 0; i < PF; ++i) {
            float dt = cdt[i];
            cum += dt;
            float u = dt * cxf[i];
#pragma unroll
            for (int j = 0; j < DH; ++j) {
                float e = ex2f(dt * A2[j]);
                s[j] = fmaf(e, s[j], u * Bv[j]);
            }
        }
    }

    size_t sb = (((size_t)bb * NC + ch) * DS + d0) * DM + c;
#pragma unroll
    for (int j = 0; j < DH; ++j) {
        g_Sloc[sb + (size_t)j * DM] = s[j];
        g_P   [sb + (size_t)j * DM] = ex2f(A2[j] * cum);
    }
}

// ---------------------------------------------------------------------------
// Kernel 3b: combine across chunks. One thread per (b, d, c).
// ---------------------------------------------------------------------------
__global__ __launch_bounds__(256)
void scan_pass2()
{
    int t  = blockIdx.x * blockDim.x + threadIdx.x;
    int bb = t / (DS * DM);
    int k  = t - bb * (DS * DM);

    float s = 0.0f;
    size_t stride = (size_t)DS * DM;
    size_t ix = ((size_t)bb * NC) * stride + k;
    for (int ch = 0; ch < NC; ++ch, ix += stride) {
        g_sinit[ix] = s;
        s = fmaf(g_P[ix], s, g_Sloc[ix]);
    }
}

// ---------------------------------------------------------------------------
// Kernel 3c: seeded rescan, pair d-SPLIT + 1 shfl + 4-step prefetch.
// ---------------------------------------------------------------------------
__global__ __launch_bounds__(256)
void scan_pass3(const float* __restrict__ Bm,
                const float* __restrict__ Cm,
                float* __restrict__ out)
{
    int bb   = blockIdx.z;
    int ch   = blockIdx.y;
    int half = threadIdx.x & 1;
    int c    = blockIdx.x * 128 + (threadIdx.x >> 1);
    int d0   = half * DH;

    float A2[DH], Bv[DH], Cv[DH], s[DH];
    size_t sb = (((size_t)bb * NC + ch) * DS + d0) * DM + c;
#pragma unroll
    for (int j = 0; j < DH; ++j) {
        A2[j] = g_A2[c * DS + d0 + j];
        Bv[j] = Bm  [c * DS + d0 + j];
        Cv[j] = Cm  [c * DS + d0 + j];
        s[j]  = g_sinit[sb + (size_t)j * DM];
    }

    size_t base = ((size_t)bb * SEQ + (size_t)ch * CHUNK) * DM + c;
    const float* pdt = g_dt + base;
    const float* pxf = g_xf + base;
    float*       py  = out  + base;

    float ndt[PF], nxf[PF], cdt[PF], cxf[PF];
#pragma unroll
    for (int i = 0; i < PF; ++i) {
        ndt[i] = __ldcs(pdt + (size_t)i * DM);
        nxf[i] = __ldcs(pxf + (size_t)i * DM);
    }

    for (int blk = 0; blk < CHUNK / PF; ++blk) {
#pragma unroll
        for (int i = 0; i < PF; ++i) { cdt[i] = ndt[i]; cxf[i] = nxf[i]; }

        if (blk + 1 < CHUNK / PF) {
            const float* q1 = pdt + (size_t)(blk + 1) * PF * DM;
            const float* q2 = pxf + (size_t)(blk + 1) * PF * DM;
#pragma unroll
            for (int i = 0; i < PF; ++i) {
                ndt[i] = __ldcs(q1 + (size_t)i * DM);
                nxf[i] = __ldcs(q2 + (size_t)i * DM);
            }
        }

#pragma unroll
        for (int i = 0; i < PF; ++i) {
            float dt = cdt[i];
            float u  = dt * cxf[i];
            float a0 = 0.f, a1 = 0.f;
#pragma unroll
            for (int j = 0; j < DH; j += 2) {
                float e0 = ex2f(dt * A2[j + 0]);
                float e1 = ex2f(dt * A2[j + 1]);
                s[j + 0] = fmaf(e0, s[j + 0], u * Bv[j + 0]);
                s[j + 1] = fmaf(e1, s[j + 1], u * Bv[j + 1]);
                a0 = fmaf(s[j + 0], Cv[j + 0], a0);
                a1 = fmaf(s[j + 1], Cv[j + 1], a1);
            }
            float acc = a0 + a1;
            float tot = acc + __shfl_xor_sync(0xFFFFFFFFu, acc, 1);
            if (half == 0) py[(size_t)(blk * PF + i) * DM] = tot;
        }
    }
}

// ---------------------------------------------------------------------------
extern "C" void kernel_launch(void* const* d_in, const int* in_sizes, int n_in,
                              void* d_out, int out_size)
{
    const float* x      = (const float*)d_in[0];  // (8,2048,1024)
    const float* a_log  = (const float*)d_in[1];  // (1024,16)
    const float* b      = (const float*)d_in[2];  // (1024,16)
    const float* c      = (const float*)d_in[3];  // (1024,16)
    const float* dt_w   = (const float*)d_in[4];  // (1024,1024)
    const float* dt_b   = (const float*)d_in[5];  // (1024,)
    const float* conv_w = (const float*)d_in[6];  // (1024,1,3)
    const float* conv_b = (const float*)d_in[7];  // (1024,)
    float* out = (float*)d_out;                   // (8,2048,1024)

    // 0) A2 table + dt_w fp16 conversion (tiny)
    aprep_kernel<<<(DM * DS + 255) / 256, 256>>>(a_log);
    wsplit_kernel<<<(DM * DM / 4 + 255) / 256, 256>>>((const float4*)dt_w);

    // 1) depthwise conv -> g_xf (fp32) + g_xh (fp16), 2 elems/thread
    conv_kernel<<<TOT / 8 / 256, 256>>>(
        (const float4*)x, (const float4*)conv_w, (const float4*)conv_b);

    // 2) dt GEMM (+sigmoid) -> g_dt  (R14 exact config)
    cudaFuncSetAttribute(gemm_dt_kernel,
                         cudaFuncAttributeMaxDynamicSharedMemorySize, GEMM_SMEM);
    dim3 ggrid(DM / 128, (BSZ * SEQ) / 128);      // (8, 128) = 1024 CTAs
    gemm_dt_kernel<<<ggrid, 256, GEMM_SMEM>>>(dt_b);

    // 3) chunked selective scan: reduce -> combine -> seeded rescan
    dim3 sgrid(DM / 128, NC, BSZ);                // (8, 32, 8)
    scan_pass1<<<sgrid, 256>>>(b);
    scan_pass2<<<(BSZ * DS * DM) / 256, 256>>>();
    scan_pass3<<<sgrid, 256>>>(b, c, out);
}